// round 16
// baseline (speedup 1.0000x reference)
#include <cuda_runtime.h>
#include <stdint.h>

// ---------------- problem constants ----------------
#define H_DIM 2048
#define I_DIM 4096
#define E_NUM 8
#define T_NUM 4096   // B*S
#define TOPK  2

#define TM 128
#define TN 64        // CTA N-tile (2 CTAs/SM)
#define TK 32        // fp32 K elements per k-block
#define NTHREADS 256 // 8 warps: 4m x 2n, warp tile 32x32
#define RS 144       // SMEM row stride bytes: 32 fp32 = 128B + 16B pad
#define TILE_A (128 * RS)    // 18432 (A tile: 128 rows)
#define TILE_H (64 * RS)     // 9216  (B-side tiles: 64 rows)

// ---------------- scratch (__device__ globals: allocation-free) ----------------
__device__ int   g_tok[T_NUM * TOPK];
__device__ float g_wgt[T_NUM * TOPK];
__device__ int   g_cnt[E_NUM];
__device__ int   g_off[E_NUM + 1];

#define NW ((size_t)E_NUM * I_DIM * H_DIM)
__device__ float g_xw[(size_t)T_NUM * H_DIM];
__device__ float g_gw[NW];
__device__ float g_uw[NW];
__device__ float g_dw[NW];
__device__ float g_inter[(size_t)T_NUM * TOPK * I_DIM];

// ---------------- helpers ----------------
__device__ __forceinline__ void cpa16(uint32_t dst, const void* src, int srcsz) {
    asm volatile("cp.async.cg.shared.global [%0], [%1], 16, %2;"
                 :: "r"(dst), "l"(src), "r"(srcsz) : "memory");
}
#define CP_COMMIT() asm volatile("cp.async.commit_group;" ::: "memory")
#define CP_WAIT(n)  asm volatile("cp.async.wait_group %0;" :: "n"(n) : "memory")

__device__ __forceinline__ uint32_t smem_u32(const void* p) {
    uint32_t a;
    asm("{ .reg .u64 t; cvta.to.shared.u64 t, %1; cvt.u32.u64 %0, t; }" : "=r"(a) : "l"(p));
    return a;
}

#define MMAT(d, a, b0, b1) \
    asm volatile("mma.sync.aligned.m16n8k8.row.col.f32.tf32.tf32.f32 " \
        "{%0,%1,%2,%3}, {%4,%5,%6,%7}, {%8,%9}, {%0,%1,%2,%3};" \
        : "+f"((d)[0]), "+f"((d)[1]), "+f"((d)[2]), "+f"((d)[3]) \
        : "r"((a)[0]), "r"((a)[1]), "r"((a)[2]), "r"((a)[3]), "r"(b0), "r"(b1))

#define LDSM4(R, addr) \
    asm volatile("ldmatrix.sync.aligned.m8n8.x4.shared.b16 {%0,%1,%2,%3}, [%4];" \
        : "=r"((R)[0]), "=r"((R)[1]), "=r"((R)[2]), "=r"((R)[3]) : "r"(addr))

__device__ __forceinline__ float rna_tf32(float f) {
    uint32_t r;
    asm("cvt.rna.tf32.f32 %0, %1;" : "=r"(r) : "f"(f));
    return __uint_as_float(r);
}

// ---------------- rounding: fp32 -> tf32 (rna) ----------------
__global__ void __launch_bounds__(256)
roundw_kernel(const float* __restrict__ s0, float* __restrict__ d0,
              const float* __restrict__ s1, float* __restrict__ d1,
              const float* __restrict__ s2, float* __restrict__ d2)
{
    const float* src = (blockIdx.y == 0) ? s0 : (blockIdx.y == 1) ? s1 : s2;
    float* dst = (blockIdx.y == 0) ? d0 : (blockIdx.y == 1) ? d1 : d2;
    size_t i = ((size_t)blockIdx.x * 256 + threadIdx.x) * 4;
    float4 v = *(const float4*)(src + i);
    v.x = rna_tf32(v.x); v.y = rna_tf32(v.y); v.z = rna_tf32(v.z); v.w = rna_tf32(v.w);
    *(float4*)(dst + i) = v;
}

__global__ void __launch_bounds__(256)
roundx_kernel(const float* __restrict__ src, float* __restrict__ dst, size_t n)
{
    size_t i = ((size_t)blockIdx.x * 256 + threadIdx.x) * 4;
    if (i >= n) return;
    float4 v = *(const float4*)(src + i);
    v.x = rna_tf32(v.x); v.y = rna_tf32(v.y); v.z = rna_tf32(v.z); v.w = rna_tf32(v.w);
    *(float4*)(dst + i) = v;
}

// ---------------- routing ----------------
__global__ void route_kernel(const unsigned* __restrict__ idx_raw,
                             const float* __restrict__ wts)
{
    __shared__ int s_flag;
    __shared__ int s_cnt[E_NUM];
    __shared__ int s_off[E_NUM + 1];
    const int tid = threadIdx.x, wid = tid >> 5, lane = tid & 31;

    if (tid == 0) s_flag = 0;
    __syncthreads();
    unsigned acc = 0;
    for (int i = 1 + 2 * tid; i < T_NUM * TOPK; i += 512) acc |= idx_raw[i];
    if (acc) atomicOr(&s_flag, 1);
    __syncthreads();
    const int is64 = (s_flag == 0) ? 1 : 0;

    const int e = wid;
    int c = 0;
    for (int base = 0; base < T_NUM; base += 32) {
        int t = base + lane;
        int e0 = is64 ? (int)idx_raw[4 * t]     : (int)idx_raw[2 * t];
        int e1 = is64 ? (int)idx_raw[4 * t + 2] : (int)idx_raw[2 * t + 1];
        c += (e0 == e || e1 == e) ? 1 : 0;
    }
#pragma unroll
    for (int o = 16; o; o >>= 1) c += __shfl_down_sync(0xffffffffu, c, o);
    if (lane == 0) s_cnt[e] = c;
    __syncthreads();
    if (tid == 0) {
        int o = 0;
        for (int i = 0; i < E_NUM; i++) { s_off[i] = o; g_off[i] = o; g_cnt[i] = s_cnt[i]; o += s_cnt[i]; }
        s_off[E_NUM] = o; g_off[E_NUM] = o;
    }
    __syncthreads();
    int p = s_off[e];
    for (int base = 0; base < T_NUM; base += 32) {
        int t = base + lane;
        int e0 = is64 ? (int)idx_raw[4 * t]     : (int)idx_raw[2 * t];
        int e1 = is64 ? (int)idx_raw[4 * t + 2] : (int)idx_raw[2 * t + 1];
        bool m = (e0 == e || e1 == e);
        float w = (e0 == e ? wts[2 * t] : 0.0f) + (e1 == e ? wts[2 * t + 1] : 0.0f);
        unsigned msk = __ballot_sync(0xffffffffu, m);
        int pos = p + __popc(msk & ((1u << lane) - 1u));
        if (m) { g_tok[pos] = t; g_wgt[pos] = w; }
        p += __popc(msk);
    }
}

// ---------------- GEMM1 (tf32, TN=64, 3-stage, 2 CTAs/SM) ----------------
// stage: A 0 (18432), G +TILE_A (9216), U +TILE_A+TILE_H (9216); ST1 = 36864
#define ST1 (TILE_A + 2 * TILE_H)
#define G1_SMEM (512 + 3 * ST1)      // 111104 -> 2 CTAs/SM

__global__ void __launch_bounds__(NTHREADS, 2)
gemm1_kernel()
{
    const int e = blockIdx.z;
    const int cnt = g_cnt[e];
    const int rowBase = blockIdx.x * TM;
    if (rowBase >= cnt) return;
    const int off = g_off[e];
    const int n0 = blockIdx.y * TN;

    extern __shared__ char smem[];
    int* s_tok = (int*)smem;
    const uint32_t sb = smem_u32(smem);

    const int tid = threadIdx.x, wid = tid >> 5, lane = tid & 31;
    const int wm = wid >> 1, wn = wid & 1;       // 4m x 2n, warp tile 32x32
    const int lr = lane >> 2, lc = lane & 3;
    const int lg = lane >> 3, l7 = lane & 7;

    if (tid < TM) { int r = rowBase + tid; s_tok[tid] = (r < cnt) ? g_tok[off + r] : -1; }
    __syncthreads();

    // A staging: row = tid>>1 (0..127), 4 chunks (64B) at (tid&1)*64
    const int arow = tid >> 1, ach = (tid & 1) * 4;
    const int aelem = ach * 4;
    const uint32_t dA = sb + 512 + (uint32_t)(arow * RS + ach * 16);
    const int atok = s_tok[arow];
    const int asz = (atok >= 0) ? 16 : 0;
    const float* xsrc = g_xw + (size_t)(atok >= 0 ? atok : 0) * H_DIM + aelem;
    // G/U staging: row = tid>>2 (0..63), 2 chunks (32B) at (tid&3)*32
    const int brow = tid >> 2, bch = (tid & 3) * 2;
    const int belem = bch * 4;
    const uint32_t dB = sb + 512 + (uint32_t)(brow * RS + bch * 16);
    const float* gsrc = g_gw + ((size_t)e * I_DIM + n0 + brow) * H_DIM + belem;
    const float* usrc = g_uw + ((size_t)e * I_DIM + n0 + brow) * H_DIM + belem;

    const uint32_t aoff = (uint32_t)((wm * 32 + ((lg & 1) << 3) + l7) * RS + ((lg >> 1) << 4));
    const uint32_t boff = (uint32_t)((wn * 32 + ((lg >> 1) << 3) + l7) * RS + ((lg & 1) << 4));

    float accG[2][4][4], accU[2][4][4];
#pragma unroll
    for (int i = 0; i < 2; i++)
#pragma unroll
        for (int j = 0; j < 4; j++)
#pragma unroll
            for (int k = 0; k < 4; k++) { accG[i][j][k] = 0.0f; accU[i][j][k] = 0.0f; }

    const int KB = H_DIM / TK;   // 64

#define G1_ISSUE(kb, st) do { \
        uint32_t sa_ = dA + (uint32_t)(st) * ST1; \
        uint32_t sg_ = dB + (uint32_t)(st) * ST1 + TILE_A; \
        uint32_t su_ = sg_ + TILE_H; \
        int kk_ = (kb) * TK; \
        cpa16(sa_,      xsrc + kk_,      asz); \
        cpa16(sa_ + 16, xsrc + kk_ + 4,  asz); \
        cpa16(sa_ + 32, xsrc + kk_ + 8,  asz); \
        cpa16(sa_ + 48, xsrc + kk_ + 12, asz); \
        cpa16(sg_,      gsrc + kk_,      16); \
        cpa16(sg_ + 16, gsrc + kk_ + 4,  16); \
        cpa16(su_,      usrc + kk_,      16); \
        cpa16(su_ + 16, usrc + kk_ + 4,  16); \
        CP_COMMIT(); \
    } while (0)

    G1_ISSUE(0, 0);
    G1_ISSUE(1, 1);

    for (int kb = 0; kb < KB; kb++) {
        if (kb + 1 < KB) { CP_WAIT(1); } else { CP_WAIT(0); }
        __syncthreads();
        if (kb + 2 < KB) G1_ISSUE(kb + 2, (kb + 2) % 3);

        const uint32_t s0 = sb + 512 + (uint32_t)((kb % 3) * ST1);
        const uint32_t sA = s0 + aoff;
        const uint32_t sG = s0 + TILE_A + boff;
        const uint32_t sU = s0 + TILE_A + TILE_H + boff;

#pragma unroll
        for (int ks = 0; ks < 4; ks++) {
            const uint32_t ka = (uint32_t)(ks * 32);
            uint32_t a[2][4];
            LDSM4(a[0], sA + ka);
            LDSM4(a[1], sA + 16 * RS + ka);
#pragma unroll
            for (int np = 0; np < 2; np++) {
                const uint32_t bo = (uint32_t)(np * 16 * RS) + ka;
                const int p = np * 2, q = np * 2 + 1;
                uint32_t bg[4], bu[4];
                LDSM4(bg, sG + bo);
                LDSM4(bu, sU + bo);
                MMAT(accG[0][p], a[0], bg[0], bg[1]);
                MMAT(accG[0][q], a[0], bg[2], bg[3]);
                MMAT(accG[1][p], a[1], bg[0], bg[1]);
                MMAT(accG[1][q], a[1], bg[2], bg[3]);
                MMAT(accU[0][p], a[0], bu[0], bu[1]);
                MMAT(accU[0][q], a[0], bu[2], bu[3]);
                MMAT(accU[1][p], a[1], bu[0], bu[1]);
                MMAT(accU[1][q], a[1], bu[2], bu[3]);
            }
        }
    }
#undef G1_ISSUE

    // epilogue: silu(g)*u, rounded to tf32, stored fp32
#pragma unroll
    for (int mt = 0; mt < 2; mt++) {
#pragma unroll
        for (int half = 0; half < 2; half++) {
            int rloc = wm * 32 + mt * 16 + lr + half * 8;
            int r = rowBase + rloc;
            if (r >= cnt) continue;
            float* dst = g_inter + (size_t)(off + r) * I_DIM + n0 + wn * 32 + lc * 2;
#pragma unroll
            for (int nt = 0; nt < 4; nt++) {
                float g0 = accG[mt][nt][half * 2 + 0], u0 = accU[mt][nt][half * 2 + 0];
                float g1 = accG[mt][nt][half * 2 + 1], u1 = accU[mt][nt][half * 2 + 1];
                float v0 = rna_tf32((g0 / (1.0f + __expf(-g0))) * u0);
                float v1 = rna_tf32((g1 / (1.0f + __expf(-g1))) * u1);
                *(float2*)(dst + nt * 8) = make_float2(v0, v1);
            }
        }
    }
}

// ---------------- GEMM2 (tf32, TN=64, 4-stage depth-3, 2 CTAs/SM) ----------------
// stage: A 0 (18432), B +TILE_A (9216); ST2 = 27648
#define ST2 (TILE_A + TILE_H)
#define G2_SMEM (1024 + 4 * ST2)     // 111616 -> 2 CTAs/SM

__global__ void __launch_bounds__(NTHREADS, 2)
gemm2_kernel(float* __restrict__ out)
{
    const int e = blockIdx.z;
    const int cnt = g_cnt[e];
    const int rowBase = blockIdx.x * TM;
    if (rowBase >= cnt) return;
    const int off = g_off[e];
    const int n0 = blockIdx.y * TN;

    extern __shared__ char smem[];
    int*   s_tok = (int*)smem;
    float* s_wgt = (float*)(smem + 512);
    const uint32_t sb = smem_u32(smem);

    const int tid = threadIdx.x, wid = tid >> 5, lane = tid & 31;
    const int wm = wid >> 1, wn = wid & 1;
    const int lr = lane >> 2, lc = lane & 3;
    const int lg = lane >> 3, l7 = lane & 7;

    if (tid < TM) {
        int r = rowBase + tid;
        s_tok[tid] = (r < cnt) ? g_tok[off + r] : -1;
        s_wgt[tid] = (r < cnt) ? g_wgt[off + r] : 0.0f;
    }
    __syncthreads();

    const int arow = tid >> 1, ach = (tid & 1) * 4;
    const int aelem = ach * 4;
    const uint32_t dA = sb + 1024 + (uint32_t)(arow * RS + ach * 16);
    const int valid = (rowBase + arow < cnt);
    const int asz = valid ? 16 : 0;
    const float* asrc = g_inter + (size_t)(off + (valid ? rowBase + arow : 0)) * I_DIM + aelem;
    const int brow = tid >> 2, bch = (tid & 3) * 2;
    const int belem = bch * 4;
    const uint32_t dB = sb + 1024 + (uint32_t)(brow * RS + bch * 16);
    const float* bsrc = g_dw + ((size_t)e * H_DIM + n0 + brow) * I_DIM + belem;

    const uint32_t aoff = (uint32_t)((wm * 32 + ((lg & 1) << 3) + l7) * RS + ((lg >> 1) << 4));
    const uint32_t boff = (uint32_t)((wn * 32 + ((lg >> 1) << 3) + l7) * RS + ((lg & 1) << 4));

    float acc[2][4][4];
#pragma unroll
    for (int i = 0; i < 2; i++)
#pragma unroll
        for (int j = 0; j < 4; j++)
#pragma unroll
            for (int k = 0; k < 4; k++) acc[i][j][k] = 0.0f;

    const int KB = I_DIM / TK;   // 128

#define G2_ISSUE(kb, st) do { \
        uint32_t sa_ = dA + (uint32_t)(st) * ST2; \
        uint32_t sb_ = dB + (uint32_t)(st) * ST2 + TILE_A; \
        int kk_ = (kb) * TK; \
        cpa16(sa_,      asrc + kk_,      asz); \
        cpa16(sa_ + 16, asrc + kk_ + 4,  asz); \
        cpa16(sa_ + 32, asrc + kk_ + 8,  asz); \
        cpa16(sa_ + 48, asrc + kk_ + 12, asz); \
        cpa16(sb_,      bsrc + kk_,      16); \
        cpa16(sb_ + 16, bsrc + kk_ + 4,  16); \
        CP_COMMIT(); \
    } while (0)

    G2_ISSUE(0, 0);
    G2_ISSUE(1, 1);
    G2_ISSUE(2, 2);

    for (int kb = 0; kb < KB; kb++) {
        if (kb <= KB - 3) { CP_WAIT(2); } else { CP_WAIT(0); }
        __syncthreads();
        if (kb + 3 < KB) G2_ISSUE(kb + 3, (kb + 3) & 3);

        const uint32_t s0 = sb + 1024 + (uint32_t)((kb & 3) * ST2);
        const uint32_t sA = s0 + aoff;
        const uint32_t sB = s0 + TILE_A + boff;

#pragma unroll
        for (int ks = 0; ks < 4; ks++) {
            const uint32_t ka = (uint32_t)(ks * 32);
            uint32_t a[2][4];
            LDSM4(a[0], sA + ka);
            LDSM4(a[1], sA + 16 * RS + ka);
#pragma unroll
            for (int np = 0; np < 2; np++) {
                const uint32_t bo = (uint32_t)(np * 16 * RS) + ka;
                const int p = np * 2, q = np * 2 + 1;
                uint32_t b[4];
                LDSM4(b, sB + bo);
                MMAT(acc[0][p], a[0], b[0], b[1]);
                MMAT(acc[0][q], a[0], b[2], b[3]);
                MMAT(acc[1][p], a[1], b[0], b[1]);
                MMAT(acc[1][q], a[1], b[2], b[3]);
            }
        }
    }
#undef G2_ISSUE

    // epilogue: weighted scatter-add
#pragma unroll
    for (int mt = 0; mt < 2; mt++) {
#pragma unroll
        for (int half = 0; half < 2; half++) {
            int rloc = wm * 32 + mt * 16 + lr + half * 8;
            int t = s_tok[rloc];
            if (t < 0) continue;
            float w = s_wgt[rloc];
            float* dst = out + (size_t)t * H_DIM + n0 + wn * 32 + lc * 2;
#pragma unroll
            for (int nt = 0; nt < 4; nt++) {
                atomicAdd(dst + nt * 8 + 0, w * acc[mt][nt][half * 2 + 0]);
                atomicAdd(dst + nt * 8 + 1, w * acc[mt][nt][half * 2 + 1]);
            }
        }
    }
}

// ---------------- launch ----------------
extern "C" void kernel_launch(void* const* d_in, const int* in_sizes, int n_in,
                              void* d_out, int out_size)
{
    const float*    x    = (const float*)d_in[0];
    const unsigned* idx  = (const unsigned*)d_in[1];
    const float*    wts  = (const float*)d_in[2];
    const float*    gate = (const float*)d_in[3];
    const float*    up   = (const float*)d_in[4];
    const float*    down = (const float*)d_in[5];
    float* out = (float*)d_out;

    static int attr_done = 0;
    if (!attr_done) {
        cudaFuncSetAttribute(gemm1_kernel, cudaFuncAttributeMaxDynamicSharedMemorySize, G1_SMEM);
        cudaFuncSetAttribute(gemm2_kernel, cudaFuncAttributeMaxDynamicSharedMemorySize, G2_SMEM);
        attr_done = 1;
    }

    cudaMemsetAsync(out, 0, (size_t)out_size * sizeof(float));
    route_kernel<<<1, 256>>>(idx, wts);

    float *gw, *uw, *dw, *xw;
    cudaGetSymbolAddress((void**)&gw, g_gw);
    cudaGetSymbolAddress((void**)&uw, g_uw);
    cudaGetSymbolAddress((void**)&dw, g_dw);
    cudaGetSymbolAddress((void**)&xw, g_xw);

    const size_t nw = NW;
    const size_t nx = (size_t)T_NUM * H_DIM;
    roundw_kernel<<<dim3((unsigned)(nw / 1024), 3), 256>>>(gate, gw, up, uw, down, dw);
    roundx_kernel<<<(unsigned)(nx / 1024), 256>>>(x, xw, nx);

    gemm1_kernel<<<dim3(T_NUM / TM, I_DIM / TN, E_NUM), NTHREADS, G1_SMEM>>>();
    gemm2_kernel<<<dim3(T_NUM / TM, H_DIM / TN, E_NUM), NTHREADS, G2_SMEM>>>(out);
}

// round 17
// speedup vs baseline: 1.1464x; 1.1464x over previous
#include <cuda_runtime.h>
#include <stdint.h>

// ---------------- problem constants ----------------
#define H_DIM 2048
#define I_DIM 4096
#define E_NUM 8
#define T_NUM 4096   // B*S
#define TOPK  2

#define TM 128
#define TN 128
#define TK 32        // fp32 K elements per k-block (128B rows)
#define NTHREADS 512
#define RS 144       // SMEM row stride bytes: 32 fp32 = 128B + 16B pad
#define TILE_B (128 * RS)   // 18432 bytes per 128-row tile

// ---------------- scratch (__device__ globals: allocation-free) ----------------
__device__ int   g_tok[T_NUM * TOPK];
__device__ float g_wgt[T_NUM * TOPK];
__device__ int   g_cnt[E_NUM];
__device__ int   g_off[E_NUM + 1];

#define NW ((size_t)E_NUM * I_DIM * H_DIM)
__device__ float g_xw[(size_t)T_NUM * H_DIM];
__device__ float g_gw[NW];
__device__ float g_uw[NW];
__device__ float g_dw[NW];
__device__ float g_inter[(size_t)T_NUM * TOPK * I_DIM];

// ---------------- helpers ----------------
__device__ __forceinline__ void cpa16(uint32_t dst, const void* src, int srcsz) {
    asm volatile("cp.async.cg.shared.global [%0], [%1], 16, %2;"
                 :: "r"(dst), "l"(src), "r"(srcsz) : "memory");
}
#define CP_COMMIT() asm volatile("cp.async.commit_group;" ::: "memory")
#define CP_WAIT(n)  asm volatile("cp.async.wait_group %0;" :: "n"(n) : "memory")

__device__ __forceinline__ uint32_t smem_u32(const void* p) {
    uint32_t a;
    asm("{ .reg .u64 t; cvta.to.shared.u64 t, %1; cvt.u32.u64 %0, t; }" : "=r"(a) : "l"(p));
    return a;
}

#define MMAT(d, a, b0, b1) \
    asm volatile("mma.sync.aligned.m16n8k8.row.col.f32.tf32.tf32.f32 " \
        "{%0,%1,%2,%3}, {%4,%5,%6,%7}, {%8,%9}, {%0,%1,%2,%3};" \
        : "+f"((d)[0]), "+f"((d)[1]), "+f"((d)[2]), "+f"((d)[3]) \
        : "r"((a)[0]), "r"((a)[1]), "r"((a)[2]), "r"((a)[3]), "r"(b0), "r"(b1))

#define LDSM4(R, addr) \
    asm volatile("ldmatrix.sync.aligned.m8n8.x4.shared.b16 {%0,%1,%2,%3}, [%4];" \
        : "=r"((R)[0]), "=r"((R)[1]), "=r"((R)[2]), "=r"((R)[3]) : "r"(addr))

__device__ __forceinline__ float rna_tf32(float f) {
    uint32_t r;
    asm("cvt.rna.tf32.f32 %0, %1;" : "=r"(r) : "f"(f));
    return __uint_as_float(r);
}

// ---------------- rounding: fp32 -> tf32 (rna) ----------------
__global__ void __launch_bounds__(256)
roundw_kernel(const float* __restrict__ s0, float* __restrict__ d0,
              const float* __restrict__ s1, float* __restrict__ d1,
              const float* __restrict__ s2, float* __restrict__ d2)
{
    const float* src = (blockIdx.y == 0) ? s0 : (blockIdx.y == 1) ? s1 : s2;
    float* dst = (blockIdx.y == 0) ? d0 : (blockIdx.y == 1) ? d1 : d2;
    size_t i = ((size_t)blockIdx.x * 256 + threadIdx.x) * 4;
    float4 v = *(const float4*)(src + i);
    v.x = rna_tf32(v.x); v.y = rna_tf32(v.y); v.z = rna_tf32(v.z); v.w = rna_tf32(v.w);
    *(float4*)(dst + i) = v;
}

__global__ void __launch_bounds__(256)
roundx_kernel(const float* __restrict__ src, float* __restrict__ dst, size_t n)
{
    size_t i = ((size_t)blockIdx.x * 256 + threadIdx.x) * 4;
    if (i >= n) return;
    float4 v = *(const float4*)(src + i);
    v.x = rna_tf32(v.x); v.y = rna_tf32(v.y); v.z = rna_tf32(v.z); v.w = rna_tf32(v.w);
    *(float4*)(dst + i) = v;
}

// ---------------- routing ----------------
__global__ void route_kernel(const unsigned* __restrict__ idx_raw,
                             const float* __restrict__ wts)
{
    __shared__ int s_flag;
    __shared__ int s_cnt[E_NUM];
    __shared__ int s_off[E_NUM + 1];
    const int tid = threadIdx.x, wid = tid >> 5, lane = tid & 31;

    if (tid == 0) s_flag = 0;
    __syncthreads();
    unsigned acc = 0;
    for (int i = 1 + 2 * tid; i < T_NUM * TOPK; i += 512) acc |= idx_raw[i];
    if (acc) atomicOr(&s_flag, 1);
    __syncthreads();
    const int is64 = (s_flag == 0) ? 1 : 0;

    const int e = wid;
    int c = 0;
    for (int base = 0; base < T_NUM; base += 32) {
        int t = base + lane;
        int e0 = is64 ? (int)idx_raw[4 * t]     : (int)idx_raw[2 * t];
        int e1 = is64 ? (int)idx_raw[4 * t + 2] : (int)idx_raw[2 * t + 1];
        c += (e0 == e || e1 == e) ? 1 : 0;
    }
#pragma unroll
    for (int o = 16; o; o >>= 1) c += __shfl_down_sync(0xffffffffu, c, o);
    if (lane == 0) s_cnt[e] = c;
    __syncthreads();
    if (tid == 0) {
        int o = 0;
        for (int i = 0; i < E_NUM; i++) { s_off[i] = o; g_off[i] = o; g_cnt[i] = s_cnt[i]; o += s_cnt[i]; }
        s_off[E_NUM] = o; g_off[E_NUM] = o;
    }
    __syncthreads();
    int p = s_off[e];
    for (int base = 0; base < T_NUM; base += 32) {
        int t = base + lane;
        int e0 = is64 ? (int)idx_raw[4 * t]     : (int)idx_raw[2 * t];
        int e1 = is64 ? (int)idx_raw[4 * t + 2] : (int)idx_raw[2 * t + 1];
        bool m = (e0 == e || e1 == e);
        float w = (e0 == e ? wts[2 * t] : 0.0f) + (e1 == e ? wts[2 * t + 1] : 0.0f);
        unsigned msk = __ballot_sync(0xffffffffu, m);
        int pos = p + __popc(msk & ((1u << lane) - 1u));
        if (m) { g_tok[pos] = t; g_wgt[pos] = w; }
        p += __popc(msk);
    }
}

// ---------------- GEMM1 (tf32, TK=32, 3-stage — round-12 winner, unchanged) ----------------
#define ST1 (3 * TILE_B)             // 55296
#define G1_SMEM (512 + 3 * ST1)      // 166400

__global__ void __launch_bounds__(NTHREADS, 1)
gemm1_kernel()
{
    const int e = blockIdx.z;
    const int cnt = g_cnt[e];
    const int rowBase = blockIdx.x * TM;
    if (rowBase >= cnt) return;
    const int off = g_off[e];
    const int n0 = blockIdx.y * TN;

    extern __shared__ char smem[];
    int* s_tok = (int*)smem;
    const uint32_t sb = smem_u32(smem);

    const int tid = threadIdx.x, wid = tid >> 5, lane = tid & 31;
    const int wm = wid >> 2, wn = wid & 3;
    const int lr = lane >> 2, lc = lane & 3;
    const int lg = lane >> 3, l7 = lane & 7;

    if (tid < TM) { int r = rowBase + tid; s_tok[tid] = (r < cnt) ? g_tok[off + r] : -1; }
    __syncthreads();

    const int srow = tid >> 2, ch2 = (tid & 3) * 2;
    const int selem = ch2 * 4;
    const uint32_t d0 = sb + 512 + (uint32_t)(srow * RS + ch2 * 16);
    const int stok = s_tok[srow];
    const int asz = (stok >= 0) ? 16 : 0;
    const float* xsrc = g_xw + (size_t)(stok >= 0 ? stok : 0) * H_DIM + selem;
    const float* gsrc = g_gw + ((size_t)e * I_DIM + n0 + srow) * H_DIM + selem;
    const float* usrc = g_uw + ((size_t)e * I_DIM + n0 + srow) * H_DIM + selem;

    const uint32_t aoff = (uint32_t)((wm * 32 + ((lg & 1) << 3) + l7) * RS + ((lg >> 1) << 4));
    const uint32_t boff = (uint32_t)((wn * 32 + ((lg >> 1) << 3) + l7) * RS + ((lg & 1) << 4));

    float accG[2][4][4], accU[2][4][4];
#pragma unroll
    for (int i = 0; i < 2; i++)
#pragma unroll
        for (int j = 0; j < 4; j++)
#pragma unroll
            for (int k = 0; k < 4; k++) { accG[i][j][k] = 0.0f; accU[i][j][k] = 0.0f; }

    const int KB = H_DIM / TK;   // 64

#define G1_ISSUE(kb, st) do { \
        uint32_t b_ = d0 + (uint32_t)(st) * ST1; \
        int kk_ = (kb) * TK; \
        cpa16(b_,                   xsrc + kk_,     asz); \
        cpa16(b_ + 16,              xsrc + kk_ + 4, asz); \
        cpa16(b_ + TILE_B,          gsrc + kk_,     16); \
        cpa16(b_ + TILE_B + 16,     gsrc + kk_ + 4, 16); \
        cpa16(b_ + 2 * TILE_B,      usrc + kk_,     16); \
        cpa16(b_ + 2 * TILE_B + 16, usrc + kk_ + 4, 16); \
        CP_COMMIT(); \
    } while (0)

    G1_ISSUE(0, 0);
    G1_ISSUE(1, 1);

    for (int kb = 0; kb < KB; kb++) {
        if (kb + 1 < KB) { CP_WAIT(1); } else { CP_WAIT(0); }
        __syncthreads();
        if (kb + 2 < KB) G1_ISSUE(kb + 2, (kb + 2) % 3);

        const uint32_t s0 = sb + 512 + (uint32_t)((kb % 3) * ST1);
        const uint32_t sA = s0 + aoff;
        const uint32_t sG = s0 + TILE_B + boff;
        const uint32_t sU = s0 + 2 * TILE_B + boff;

#pragma unroll
        for (int ks = 0; ks < 4; ks++) {
            const uint32_t ka = (uint32_t)(ks * 32);
            uint32_t a[2][4];
            LDSM4(a[0], sA + ka);
            LDSM4(a[1], sA + 16 * RS + ka);
#pragma unroll
            for (int np = 0; np < 2; np++) {
                const uint32_t bo = (uint32_t)(np * 16 * RS) + ka;
                const int p = np * 2, q = np * 2 + 1;
                uint32_t bg[4], bu[4];
                LDSM4(bg, sG + bo);
                LDSM4(bu, sU + bo);
                MMAT(accG[0][p], a[0], bg[0], bg[1]);
                MMAT(accG[0][q], a[0], bg[2], bg[3]);
                MMAT(accG[1][p], a[1], bg[0], bg[1]);
                MMAT(accG[1][q], a[1], bg[2], bg[3]);
                MMAT(accU[0][p], a[0], bu[0], bu[1]);
                MMAT(accU[0][q], a[0], bu[2], bu[3]);
                MMAT(accU[1][p], a[1], bu[0], bu[1]);
                MMAT(accU[1][q], a[1], bu[2], bu[3]);
            }
        }
    }
#undef G1_ISSUE

    // epilogue: silu(g)*u, rounded to tf32, stored fp32
#pragma unroll
    for (int mt = 0; mt < 2; mt++) {
#pragma unroll
        for (int half = 0; half < 2; half++) {
            int rloc = wm * 32 + mt * 16 + lr + half * 8;
            int r = rowBase + rloc;
            if (r >= cnt) continue;
            float* dst = g_inter + (size_t)(off + r) * I_DIM + n0 + wn * 32 + lc * 2;
#pragma unroll
            for (int nt = 0; nt < 4; nt++) {
                float g0 = accG[mt][nt][half * 2 + 0], u0 = accU[mt][nt][half * 2 + 0];
                float g1 = accG[mt][nt][half * 2 + 1], u1 = accU[mt][nt][half * 2 + 1];
                float v0 = rna_tf32((g0 / (1.0f + __expf(-g0))) * u0);
                float v1 = rna_tf32((g1 / (1.0f + __expf(-g1))) * u1);
                *(float2*)(dst + nt * 8) = make_float2(v0, v1);
            }
        }
    }
}

// ---------------- GEMM2 (tf32, TK=32, pair-processed: 2 k-blocks per barrier, 6 stages) ----------------
#define ST2 (2 * TILE_B)             // 36864 per block-stage
#define G2_SMEM (1024 + 6 * ST2)     // 222208

__global__ void __launch_bounds__(NTHREADS, 1)
gemm2_kernel(float* __restrict__ out)
{
    const int e = blockIdx.z;
    const int cnt = g_cnt[e];
    const int rowBase = blockIdx.x * TM;
    if (rowBase >= cnt) return;
    const int off = g_off[e];
    const int n0 = blockIdx.y * TN;

    extern __shared__ char smem[];
    int*   s_tok = (int*)smem;
    float* s_wgt = (float*)(smem + 512);
    const uint32_t sb = smem_u32(smem);

    const int tid = threadIdx.x, wid = tid >> 5, lane = tid & 31;
    const int wm = wid >> 2, wn = wid & 3;
    const int lr = lane >> 2, lc = lane & 3;
    const int lg = lane >> 3, l7 = lane & 7;

    if (tid < TM) {
        int r = rowBase + tid;
        s_tok[tid] = (r < cnt) ? g_tok[off + r] : -1;
        s_wgt[tid] = (r < cnt) ? g_wgt[off + r] : 0.0f;
    }
    __syncthreads();

    const int srow = tid >> 2, ch2 = (tid & 3) * 2;
    const int selem = ch2 * 4;
    const uint32_t d0 = sb + 1024 + (uint32_t)(srow * RS + ch2 * 16);
    const int valid = (rowBase + srow < cnt);
    const int asz = valid ? 16 : 0;
    const float* asrc = g_inter + (size_t)(off + (valid ? rowBase + srow : 0)) * I_DIM + selem;
    const float* bsrc = g_dw + ((size_t)e * H_DIM + n0 + srow) * I_DIM + selem;

    const uint32_t aoff = (uint32_t)((wm * 32 + ((lg & 1) << 3) + l7) * RS + ((lg >> 1) << 4));
    const uint32_t boff = (uint32_t)((wn * 32 + ((lg >> 1) << 3) + l7) * RS + ((lg & 1) << 4));

    float acc[2][4][4];
#pragma unroll
    for (int i = 0; i < 2; i++)
#pragma unroll
        for (int j = 0; j < 4; j++)
#pragma unroll
            for (int k = 0; k < 4; k++) acc[i][j][k] = 0.0f;

    const int NP = (I_DIM / TK) / 2;   // 64 pairs

    // pair j occupies set j%3; block b of pair j at set base + (b&1)*ST2
#define G2_ISSUE_BLK(kb, stg) do { \
        uint32_t b_ = d0 + (uint32_t)(stg) * ST2; \
        int kk_ = (kb) * TK; \
        cpa16(b_,               asrc + kk_,     asz); \
        cpa16(b_ + 16,          asrc + kk_ + 4, asz); \
        cpa16(b_ + TILE_B,      bsrc + kk_,     16); \
        cpa16(b_ + TILE_B + 16, bsrc + kk_ + 4, 16); \
    } while (0)
#define G2_ISSUE_PAIR(j) do { \
        int set_ = (j) % 3; \
        G2_ISSUE_BLK(2 * (j),     set_ * 2); \
        G2_ISSUE_BLK(2 * (j) + 1, set_ * 2 + 1); \
        CP_COMMIT(); \
    } while (0)

#define G2_COMPUTE(stg) do { \
        const uint32_t s0_ = sb + 1024 + (uint32_t)(stg) * ST2; \
        const uint32_t sA_ = s0_ + aoff; \
        const uint32_t sB_ = s0_ + TILE_B + boff; \
        _Pragma("unroll") \
        for (int ks = 0; ks < 4; ks++) { \
            const uint32_t ka = (uint32_t)(ks * 32); \
            uint32_t a[2][4]; \
            LDSM4(a[0], sA_ + ka); \
            LDSM4(a[1], sA_ + 16 * RS + ka); \
            _Pragma("unroll") \
            for (int np = 0; np < 2; np++) { \
                const uint32_t bo = (uint32_t)(np * 16 * RS) + ka; \
                const int p = np * 2, q = np * 2 + 1; \
                uint32_t b[4]; \
                LDSM4(b, sB_ + bo); \
                MMAT(acc[0][p], a[0], b[0], b[1]); \
                MMAT(acc[0][q], a[0], b[2], b[3]); \
                MMAT(acc[1][p], a[1], b[0], b[1]); \
                MMAT(acc[1][q], a[1], b[2], b[3]); \
            } \
        } \
    } while (0)

    G2_ISSUE_PAIR(0);
    G2_ISSUE_PAIR(1);

    for (int j = 0; j < NP; j++) {
        if (j + 2 < NP) { CP_WAIT(1); } else { CP_WAIT(0); }
        __syncthreads();
        if (j + 2 < NP) G2_ISSUE_PAIR(j + 2);

        const int set = j % 3;
        G2_COMPUTE(set * 2);
        G2_COMPUTE(set * 2 + 1);
    }
#undef G2_ISSUE_BLK
#undef G2_ISSUE_PAIR
#undef G2_COMPUTE

    // epilogue: weighted scatter-add
#pragma unroll
    for (int mt = 0; mt < 2; mt++) {
#pragma unroll
        for (int half = 0; half < 2; half++) {
            int rloc = wm * 32 + mt * 16 + lr + half * 8;
            int t = s_tok[rloc];
            if (t < 0) continue;
            float w = s_wgt[rloc];
            float* dst = out + (size_t)t * H_DIM + n0 + wn * 32 + lc * 2;
#pragma unroll
            for (int nt = 0; nt < 4; nt++) {
                atomicAdd(dst + nt * 8 + 0, w * acc[mt][nt][half * 2 + 0]);
                atomicAdd(dst + nt * 8 + 1, w * acc[mt][nt][half * 2 + 1]);
            }
        }
    }
}

// ---------------- launch ----------------
extern "C" void kernel_launch(void* const* d_in, const int* in_sizes, int n_in,
                              void* d_out, int out_size)
{
    const float*    x    = (const float*)d_in[0];
    const unsigned* idx  = (const unsigned*)d_in[1];
    const float*    wts  = (const float*)d_in[2];
    const float*    gate = (const float*)d_in[3];
    const float*    up   = (const float*)d_in[4];
    const float*    down = (const float*)d_in[5];
    float* out = (float*)d_out;

    static int attr_done = 0;
    if (!attr_done) {
        cudaFuncSetAttribute(gemm1_kernel, cudaFuncAttributeMaxDynamicSharedMemorySize, G1_SMEM);
        cudaFuncSetAttribute(gemm2_kernel, cudaFuncAttributeMaxDynamicSharedMemorySize, G2_SMEM);
        attr_done = 1;
    }

    cudaMemsetAsync(out, 0, (size_t)out_size * sizeof(float));
    route_kernel<<<1, 256>>>(idx, wts);

    float *gw, *uw, *dw, *xw;
    cudaGetSymbolAddress((void**)&gw, g_gw);
    cudaGetSymbolAddress((void**)&uw, g_uw);
    cudaGetSymbolAddress((void**)&dw, g_dw);
    cudaGetSymbolAddress((void**)&xw, g_xw);

    const size_t nw = NW;
    const size_t nx = (size_t)T_NUM * H_DIM;
    roundw_kernel<<<dim3((unsigned)(nw / 1024), 3), 256>>>(gate, gw, up, uw, down, dw);
    roundx_kernel<<<(unsigned)(nx / 1024), 256>>>(x, xw, nx);

    gemm1_kernel<<<dim3(T_NUM / TM, I_DIM / TN, E_NUM), NTHREADS, G1_SMEM>>>();
    gemm2_kernel<<<dim3(T_NUM / TM, H_DIM / TN, E_NUM), NTHREADS, G2_SMEM>>>(out);
}